// round 16
// baseline (speedup 1.0000x reference)
#include <cuda_runtime.h>

// ChamferLoss: B=4, N=M=8192, D=3
// Role-swapped fused tiles: each thread holds 8 CANDIDATES (4 packed pairs) in
// registers; 512 QUERIES rotate through shared. Col mins accumulate in
// registers (thread-owned candidates); row mins via per-warp rotation RMW in
// shared. dist = a^2 + b^2 - 2 a.b, all FMA work packed f32x2.

#define TPB     128
#define CPT     4                   // candidate pairs per thread (8 cands)
#define QTILE   512                 // queries per block
#define NPTS    8192
#define NB      4
#define CTILE   (TPB * CPT * 2)     // 1024 candidates per block
#define QCH     (NPTS / QTILE)      // 16
#define CCH     (NPTS / CTILE)      // 8
#define NSLOT   (NB * NPTS)         // 32768
#define F1BLK   64

__device__ float g_row[CCH][NSLOT];   // row-min partial per candidate-chunk
__device__ float g_col[QCH][NSLOT];   // col-min partial per query-chunk
__device__ float g_part[F1BLK];

typedef unsigned long long u64;

__device__ __forceinline__ u64 ffma2(u64 a, u64 b, u64 c) {
    u64 d;
    asm("fma.rn.f32x2 %0, %1, %2, %3;" : "=l"(d) : "l"(a), "l"(b), "l"(c));
    return d;
}
__device__ __forceinline__ u64 fadd2(u64 a, u64 b) {
    u64 d;
    asm("add.rn.f32x2 %0, %1, %2;" : "=l"(d) : "l"(a), "l"(b));
    return d;
}
__device__ __forceinline__ u64 pack2(float lo, float hi) {
    u64 d;
    asm("mov.b64 %0, {%1, %2};" : "=l"(d) : "f"(lo), "f"(hi));
    return d;
}
__device__ __forceinline__ void unpack2(u64 v, float& lo, float& hi) {
    asm("mov.b64 {%0, %1}, %2;" : "=f"(lo), "=f"(hi) : "l"(v));
}

__global__ __launch_bounds__(TPB, 7) void chamfer_tile_kernel(
    const float* __restrict__ p1, const float* __restrict__ p2)
{
    const int qc = blockIdx.x;            // query chunk (16)
    const int b  = blockIdx.y;            // batch (4)
    const int cc = blockIdx.z;            // candidate chunk (8)
    const float* __restrict__ q = p1 + (size_t)b * NPTS * 3;   // queries
    const float* __restrict__ d = p2 + (size_t)b * NPTS * 3;   // candidates

    const int tid  = threadIdx.x;
    const int lane = tid & 31;
    const int w    = tid >> 5;
    const int qbase = qc * QTILE;
    const int cbase = cc * CTILE;

    __shared__ ulonglong2 sQ1[QTILE];     // (cx|cx, cy|cy) packed coeffs
    __shared__ ulonglong2 sQ2[QTILE];     // (cz|cz, a2|a2)
    __shared__ float sRow[4][QTILE];      // per-warp row mins

    // ---- 8 candidates into registers (4 packed pairs) ----
    u64 xx[CPT], yy[CPT], zz[CPT], ww[CPT];
    {
        const float4* csrc = (const float4*)(d + (size_t)(cbase + tid * 8) * 3);
        float cf[24];
        #pragma unroll
        for (int v = 0; v < 6; ++v)
            *(float4*)&cf[4 * v] = csrc[v];
        #pragma unroll
        for (int p = 0; p < CPT; ++p) {
            const int f = 6 * p;
            xx[p] = pack2(cf[f + 0], cf[f + 3]);
            yy[p] = pack2(cf[f + 1], cf[f + 4]);
            zz[p] = pack2(cf[f + 2], cf[f + 5]);
            const float w0 = cf[f+0]*cf[f+0] + cf[f+1]*cf[f+1] + cf[f+2]*cf[f+2];
            const float w1 = cf[f+3]*cf[f+3] + cf[f+4]*cf[f+4] + cf[f+5]*cf[f+5];
            ww[p] = pack2(w0, w1);
        }
    }

    // ---- query tile: packed coefficients ----
    #pragma unroll
    for (int k = 0; k < QTILE / TPB; ++k) {
        const int i = k * TPB + tid;
        const int gi = qbase + i;
        const float ax = q[3 * gi + 0], ay = q[3 * gi + 1], az = q[3 * gi + 2];
        const float a2 = ax * ax + ay * ay + az * az;
        sQ1[i] = make_ulonglong2(pack2(-2.0f * ax, -2.0f * ax),
                                 pack2(-2.0f * ay, -2.0f * ay));
        sQ2[i] = make_ulonglong2(pack2(-2.0f * az, -2.0f * az),
                                 pack2(a2, a2));
        #pragma unroll
        for (int ww2 = 0; ww2 < 4; ++ww2)
            sRow[ww2][i] = 3.4e38f;
    }
    __syncthreads();

    // ---- col accumulators in registers ----
    float colE[CPT], colO[CPT];
    #pragma unroll
    for (int p = 0; p < CPT; ++p) { colE[p] = 3.4e38f; colO[p] = 3.4e38f; }

    // rotation over queries: round r, lane l -> query (l+r)&511; lanes within
    // a warp hit distinct queries, so per-warp row RMW is race-free.
    #pragma unroll 4
    for (int r = 0; r < QTILE; ++r) {
        const int j = (lane + r) & (QTILE - 1);
        const ulonglong2 q1 = sQ1[j];     // (cx, cy)
        const ulonglong2 q2 = sQ2[j];     // (cz, a2)

        u64 dd[CPT];
        #pragma unroll
        for (int p = 0; p < CPT; ++p) dd[p] = ffma2(q2.x, zz[p], ww[p]);
        #pragma unroll
        for (int p = 0; p < CPT; ++p) dd[p] = ffma2(q1.y, yy[p], dd[p]);
        #pragma unroll
        for (int p = 0; p < CPT; ++p) dd[p] = ffma2(q1.x, xx[p], dd[p]);
        #pragma unroll
        for (int p = 0; p < CPT; ++p) dd[p] = fadd2(dd[p], q2.y);  // + a^2

        float lo[CPT], hi[CPT];
        #pragma unroll
        for (int p = 0; p < CPT; ++p) {
            unpack2(dd[p], lo[p], hi[p]);
            colE[p] = fminf(colE[p], lo[p]);
            colO[p] = fminf(colO[p], hi[p]);
        }
        // row min for query j over this thread's 8 candidates
        const float rmin = fminf(fminf(fminf(lo[0], hi[0]), fminf(lo[1], hi[1])),
                                 fminf(fminf(lo[2], hi[2]), fminf(lo[3], hi[3])));
        sRow[w][j] = fminf(sRow[w][j], rmin);
    }

    __syncthreads();

    // row partials: combine 4 warp copies, store coalesced
    {
        float* dst = &g_row[cc][b * NPTS + qbase];
        #pragma unroll
        for (int k = 0; k < QTILE / TPB; ++k) {
            const int i = k * TPB + tid;
            dst[i] = fminf(fminf(sRow[0][i], sRow[1][i]),
                           fminf(sRow[2][i], sRow[3][i]));
        }
    }

    // col partials: thread-owned 8 candidates (already include a^2... = full dist)
    {
        float* dst = &g_col[qc][b * NPTS + cbase + tid * 8];
        float4 v0 = make_float4(colE[0], colO[0], colE[1], colO[1]);
        float4 v1 = make_float4(colE[2], colO[2], colE[3], colO[3]);
        *(float4*)(dst + 0) = v0;
        *(float4*)(dst + 4) = v1;
    }
}

__global__ __launch_bounds__(256) void chamfer_finalize1(void)
{
    __shared__ float red[8];
    const int t = blockIdx.x * 256 + threadIdx.x;   // 16384 threads
    float s = 0.0f;
    #pragma unroll
    for (int r = 0; r < NSLOT / 16384; ++r) {       // 2 row + 2 col slots/thread
        const int f = t + r * 16384;
        float m = g_row[0][f];
        #pragma unroll
        for (int c = 1; c < CCH; ++c) m = fminf(m, g_row[c][f]);
        s += m;
        float m2 = g_col[0][f];
        #pragma unroll
        for (int c = 1; c < QCH; ++c) m2 = fminf(m2, g_col[c][f]);
        s += m2;
    }
    #pragma unroll
    for (int o = 16; o > 0; o >>= 1)
        s += __shfl_down_sync(0xffffffffu, s, o);
    if ((threadIdx.x & 31) == 0) red[threadIdx.x >> 5] = s;
    __syncthreads();
    if (threadIdx.x < 8) {
        s = red[threadIdx.x];
        #pragma unroll
        for (int o = 4; o > 0; o >>= 1)
            s += __shfl_down_sync(0xffu, s, o);
        if (threadIdx.x == 0) g_part[blockIdx.x] = s;
    }
}

__global__ void chamfer_finalize2(float* __restrict__ out)
{
    __shared__ float red[2];
    float v = g_part[threadIdx.x];   // 64 threads
    #pragma unroll
    for (int o = 16; o > 0; o >>= 1)
        v += __shfl_down_sync(0xffffffffu, v, o);
    if ((threadIdx.x & 31) == 0) red[threadIdx.x >> 5] = v;
    __syncthreads();
    if (threadIdx.x == 0)
        out[0] = (red[0] + red[1]) * (1.0f / (float)(NB * NPTS));
}

extern "C" void kernel_launch(void* const* d_in, const int* in_sizes, int n_in,
                              void* d_out, int out_size)
{
    const float* p1 = (const float*)d_in[0];
    const float* p2 = (const float*)d_in[1];
    float* out = (float*)d_out;

    dim3 grid(QCH, NB, CCH);   // 16 x 4 x 8 = 512 blocks
    chamfer_tile_kernel<<<grid, TPB>>>(p1, p2);
    chamfer_finalize1<<<F1BLK, 256>>>();
    chamfer_finalize2<<<1, F1BLK>>>(out);
}